// round 10
// baseline (speedup 1.0000x reference)
#include <cuda_runtime.h>
#include <stdint.h>

#define N_PTS 16384
#define GS 64
#define NCELL (GS * GS * GS)           // 262144
#define CAP 16
#define OVCAP 1024
#define OX (-5.5f)
#define CELL_SZ 0.171875f              // 11/64
#define INV_CELL 5.8181818f            // 64/11
#define QTPB 256
#define WARPS_PB (QTPB / 32)           // 8
#define QBLOCKS (2 * N_PTS / WARPS_PB) // 4096

__device__ int    g_cnt[2][NCELL];              // per-cell count / slot cursor
__device__ float4 g_cell_pts[2][NCELL * CAP];   // direct per-cell storage (sparse-hot)
__device__ int    g_ovcnt[2];
__device__ float4 g_ovpts[2][OVCAP];
__device__ float  g_bsum[QBLOCKS];
__device__ int    g_done;

__global__ void cd_zero() {
    int i = blockIdx.x * blockDim.x + threadIdx.x;
    int stride = gridDim.x * blockDim.x;
    int* c = (int*)g_cnt;
    for (int k = i; k < 2 * NCELL; k += stride) c[k] = 0;
    if (i == 0) { g_ovcnt[0] = 0; g_ovcnt[1] = 0; g_done = 0; }
}

__device__ __forceinline__ int cell_coord(float v) {
    int c = (int)floorf((v - OX) * INV_CELL);
    return min(max(c, 0), GS - 1);
}

__global__ void cd_build(const float* __restrict__ pred, const float* __restrict__ gt) {
    int t = blockIdx.x * blockDim.x + threadIdx.x;   // 0..32767
    int dir = t >> 14;
    int i = t & (N_PTS - 1);
    const float* P = dir ? pred : gt;                 // dir0 db=gt, dir1 db=pred
    float x = P[3 * i], y = P[3 * i + 1], z = P[3 * i + 2];
    int cx = cell_coord(x), cy = cell_coord(y), cz = cell_coord(z);
    int cell = (cz * GS + cy) * GS + cx;
    int slot = atomicAdd(&g_cnt[dir][cell], 1);
    float4 v = make_float4(x, y, z, 0.0f);
    if (slot < CAP) {
        g_cell_pts[dir][cell * CAP + slot] = v;
    } else {
        int o = atomicAdd(&g_ovcnt[dir], 1);
        if (o < OVCAP) g_ovpts[dir][o] = v;
    }
}

// One warp per query; fused final reduction via last-block-done.
__global__ void __launch_bounds__(QTPB) cd_query(
    const float* __restrict__ pred, const float* __restrict__ gt,
    float* __restrict__ out)
{
    const int wid  = (blockIdx.x * QTPB + threadIdx.x) >> 5;   // 0..32767
    const int lane = threadIdx.x & 31;
    const int dir  = wid >> 14;
    const int i    = wid & (N_PTS - 1);

    const float* Q = dir ? gt : pred;
    const float qx = Q[3 * i], qy = Q[3 * i + 1], qz = Q[3 * i + 2];
    const int cx = cell_coord(qx), cy = cell_coord(qy), cz = cell_coord(qz);

    const int*    __restrict__ cnts = g_cnt[dir];
    const float4* __restrict__ pts  = g_cell_pts[dir];

    float best_l = 3.402823466e+38f;

    // ---- r = 1 specialized: lanes 0..26 = 3x3x3 cells, constant-divisor decode,
    //      header + first-4 points loaded speculatively in one latency round. ----
    {
        int dz = lane / 9;               // constant divisors -> IMAD magic
        int rem = lane - dz * 9;
        int dy = rem / 3;
        int dx = rem - dy * 3;
        int z = cz - 1 + dz, y = cy - 1 + dy, x = cx - 1 + dx;
        bool valid = (lane < 27) && (unsigned)z < GS && (unsigned)y < GS && (unsigned)x < GS;
        int cell = valid ? (z * GS + y) * GS + x : 0;
        int n = valid ? min(cnts[cell], CAP) : 0;
        const float4* row = pts + cell * CAP;
        // speculative: addresses independent of n; junk masked by k<n
        float4 p0 = row[0], p1 = row[1], p2 = row[2], p3 = row[3];
        float d0, d1, d2c, d3;
        {
            float ddx = qx - p0.x, ddy = qy - p0.y, ddz = qz - p0.z;
            d0 = fmaf(ddx, ddx, fmaf(ddy, ddy, ddz * ddz));
            ddx = qx - p1.x; ddy = qy - p1.y; ddz = qz - p1.z;
            d1 = fmaf(ddx, ddx, fmaf(ddy, ddy, ddz * ddz));
            ddx = qx - p2.x; ddy = qy - p2.y; ddz = qz - p2.z;
            d2c = fmaf(ddx, ddx, fmaf(ddy, ddy, ddz * ddz));
            ddx = qx - p3.x; ddy = qy - p3.y; ddz = qz - p3.z;
            d3 = fmaf(ddx, ddx, fmaf(ddy, ddy, ddz * ddz));
        }
        if (n > 0) best_l = fminf(best_l, d0);
        if (n > 1) best_l = fminf(best_l, d1);
        if (n > 2) best_l = fminf(best_l, d2c);
        if (n > 3) best_l = fminf(best_l, d3);
        for (int k = 4; k < n; ++k) {
            float4 p = row[k];
            float ddx = qx - p.x, ddy = qy - p.y, ddz = qz - p.z;
            best_l = fminf(best_l, fmaf(ddx, ddx, fmaf(ddy, ddy, ddz * ddz)));
        }
    }

    bool done = false;
    {
        float bw = best_l;
        for (int o = 16; o > 0; o >>= 1)
            bw = fminf(bw, __shfl_xor_sync(0xFFFFFFFFu, bw, o));
        float mxlo = (cx - 1 <= 0)      ? 1e30f : qx - (OX + (float)(cx - 1) * CELL_SZ);
        float mxhi = (cx + 1 >= GS - 1) ? 1e30f : (OX + (float)(cx + 2) * CELL_SZ) - qx;
        float mylo = (cy - 1 <= 0)      ? 1e30f : qy - (OX + (float)(cy - 1) * CELL_SZ);
        float myhi = (cy + 1 >= GS - 1) ? 1e30f : (OX + (float)(cy + 2) * CELL_SZ) - qy;
        float mzlo = (cz - 1 <= 0)      ? 1e30f : qz - (OX + (float)(cz - 1) * CELL_SZ);
        float mzhi = (cz + 1 >= GS - 1) ? 1e30f : (OX + (float)(cz + 2) * CELL_SZ) - qz;
        float m = fminf(fminf(fminf(mxlo, mxhi), fminf(mylo, myhi)), fminf(mzlo, mzhi));
        m = fmaxf(m, 0.0f);
        done = (bw <= m * m);
    }

    // ---- r >= 2 fallback (rare stragglers) ----
    if (!done) {
        for (int r = 2; r <= GS; ++r) {
            const int u = 2 * r + 1;
            const int uu = u * u;
            const int total = u * uu;
            for (int base = 0; base < total; base += 32) {
                int ci = base + lane;
                if (ci < total) {
                    int dz = ci / uu;
                    int rem = ci - dz * uu;
                    int dy = rem / u;
                    int dx = rem - dy * u;
                    int cheb = max(max(abs(dz - r), abs(dy - r)), abs(dx - r));
                    int z = cz - r + dz, y = cy - r + dy, x = cx - r + dx;
                    bool ok = (cheb == r) &&
                              (unsigned)z < GS && (unsigned)y < GS && (unsigned)x < GS;
                    if (ok) {
                        int cell = (z * GS + y) * GS + x;
                        int n = min(cnts[cell], CAP);
                        const float4* row = pts + cell * CAP;
                        for (int k = 0; k < n; ++k) {
                            float4 p = row[k];
                            float ddx = qx - p.x, ddy = qy - p.y, ddz = qz - p.z;
                            best_l = fminf(best_l, fmaf(ddx, ddx, fmaf(ddy, ddy, ddz * ddz)));
                        }
                    }
                }
            }
            float bw = best_l;
            for (int o = 16; o > 0; o >>= 1)
                bw = fminf(bw, __shfl_xor_sync(0xFFFFFFFFu, bw, o));
            float mxlo = (cx - r <= 0)      ? 1e30f : qx - (OX + (float)(cx - r) * CELL_SZ);
            float mxhi = (cx + r >= GS - 1) ? 1e30f : (OX + (float)(cx + r + 1) * CELL_SZ) - qx;
            float mylo = (cy - r <= 0)      ? 1e30f : qy - (OX + (float)(cy - r) * CELL_SZ);
            float myhi = (cy + r >= GS - 1) ? 1e30f : (OX + (float)(cy + r + 1) * CELL_SZ) - qy;
            float mzlo = (cz - r <= 0)      ? 1e30f : qz - (OX + (float)(cz - r) * CELL_SZ);
            float mzhi = (cz + r >= GS - 1) ? 1e30f : (OX + (float)(cz + r + 1) * CELL_SZ) - qz;
            float m = fminf(fminf(fminf(mxlo, mxhi), fminf(mylo, myhi)), fminf(mzlo, mzhi));
            m = fmaxf(m, 0.0f);
            if (bw <= m * m) break;
        }
    }

    // overflow points (rarely nonempty)
    int on = min(g_ovcnt[dir], OVCAP);
    for (int k = lane; k < on; k += 32) {
        float4 p = g_ovpts[dir][k];
        float ddx = qx - p.x, ddy = qy - p.y, ddz = qz - p.z;
        best_l = fminf(best_l, fmaf(ddx, ddx, fmaf(ddy, ddy, ddz * ddz)));
    }
    for (int o = 16; o > 0; o >>= 1)
        best_l = fminf(best_l, __shfl_xor_sync(0xFFFFFFFFu, best_l, o));

    // per-block deterministic sum
    __shared__ float swarp[WARPS_PB];
    __shared__ int slast;
    if (lane == 0) swarp[threadIdx.x >> 5] = sqrtf(best_l);
    __syncthreads();
    if (threadIdx.x == 0) {
        float tot = 0.0f;
#pragma unroll
        for (int w = 0; w < WARPS_PB; ++w) tot += swarp[w];
        g_bsum[blockIdx.x] = tot;
        __threadfence();
        int prev = atomicAdd(&g_done, 1);
        slast = (prev == QBLOCKS - 1) ? 1 : 0;
    }
    __syncthreads();

    // last block performs the (deterministic, fixed-order) final reduction
    if (slast) {
        float s = 0.0f;
        for (int k = threadIdx.x; k < QBLOCKS; k += QTPB) s += g_bsum[k];
        for (int o = 16; o > 0; o >>= 1) s += __shfl_xor_sync(0xFFFFFFFFu, s, o);
        __shared__ float ssum[WARPS_PB];
        if ((threadIdx.x & 31) == 0) ssum[threadIdx.x >> 5] = s;
        __syncthreads();
        if (threadIdx.x == 0) {
            float tot = 0.0f;
#pragma unroll
            for (int w = 0; w < WARPS_PB; ++w) tot += ssum[w];
            out[0] = tot / (float)N_PTS;
        }
    }
}

extern "C" void kernel_launch(void* const* d_in, const int* in_sizes, int n_in,
                              void* d_out, int out_size) {
    const float* pred = (const float*)d_in[0];
    const float* gt   = (const float*)d_in[1];
    float* out = (float*)d_out;

    cd_zero<<<512, 256>>>();
    cd_build<<<(2 * N_PTS) / 256, 256>>>(pred, gt);
    cd_query<<<QBLOCKS, QTPB>>>(pred, gt, out);
}

// round 11
// speedup vs baseline: 2.5665x; 2.5665x over previous
#include <cuda_runtime.h>
#include <stdint.h>

#define N_PTS 16384
#define GS 64
#define NCELL (GS * GS * GS)           // 262144
#define CAP 16
#define OVCAP 1024
#define OX (-5.5f)
#define CELL_SZ 0.171875f              // 11/64
#define INV_CELL 5.8181818f            // 64/11
#define QTPB 256
#define WARPS_PB (QTPB / 32)           // 8
#define QBLOCKS (2 * N_PTS / WARPS_PB) // 4096

__device__ int    g_cnt[2][NCELL];              // per-cell count / slot cursor
__device__ float4 g_cell_pts[2][NCELL * CAP];   // direct per-cell storage (sparse-hot)
__device__ float4 g_db[2][N_PTS];               // compact all-points array (brute fallback)
__device__ int    g_ovcnt[2];
__device__ float4 g_ovpts[2][OVCAP];
__device__ float  g_bsum[QBLOCKS];
__device__ int    g_done;

__global__ void cd_zero() {
    int i = blockIdx.x * blockDim.x + threadIdx.x;
    int stride = gridDim.x * blockDim.x;
    int* c = (int*)g_cnt;
    for (int k = i; k < 2 * NCELL; k += stride) c[k] = 0;
    if (i == 0) { g_ovcnt[0] = 0; g_ovcnt[1] = 0; g_done = 0; }
}

__device__ __forceinline__ int cell_coord(float v) {
    int c = (int)floorf((v - OX) * INV_CELL);
    return min(max(c, 0), GS - 1);
}

__global__ void cd_build(const float* __restrict__ pred, const float* __restrict__ gt) {
    int t = blockIdx.x * blockDim.x + threadIdx.x;   // 0..32767
    int dir = t >> 14;
    int i = t & (N_PTS - 1);
    const float* P = dir ? pred : gt;                 // dir0 db=gt, dir1 db=pred
    float x = P[3 * i], y = P[3 * i + 1], z = P[3 * i + 2];
    float4 v = make_float4(x, y, z, 0.0f);
    g_db[dir][i] = v;
    int cx = cell_coord(x), cy = cell_coord(y), cz = cell_coord(z);
    int cell = (cz * GS + cy) * GS + cx;
    int slot = atomicAdd(&g_cnt[dir][cell], 1);
    if (slot < CAP) {
        g_cell_pts[dir][cell * CAP + slot] = v;
    } else {
        int o = atomicAdd(&g_ovcnt[dir], 1);
        if (o < OVCAP) g_ovpts[dir][o] = v;
    }
}

// One warp per query: r=1 probe; if the AABB-margin bound can't certify the
// result, fall back to a warp-parallel brute scan of the whole db (bounded cost).
__global__ void __launch_bounds__(QTPB) cd_query(
    const float* __restrict__ pred, const float* __restrict__ gt,
    float* __restrict__ out)
{
    const int wid  = (blockIdx.x * QTPB + threadIdx.x) >> 5;   // 0..32767
    const int lane = threadIdx.x & 31;
    const int dir  = wid >> 14;
    const int i    = wid & (N_PTS - 1);

    const float* Q = dir ? gt : pred;
    const float qx = Q[3 * i], qy = Q[3 * i + 1], qz = Q[3 * i + 2];
    const int cx = cell_coord(qx), cy = cell_coord(qy), cz = cell_coord(qz);

    const int*    __restrict__ cnts = g_cnt[dir];
    const float4* __restrict__ pts  = g_cell_pts[dir];

    float best_l = 3.402823466e+38f;

    // ---- r=1 probe: lanes 0..26 cover the 3x3x3 box ----
    {
        int dz = lane / 9;
        int rem = lane - dz * 9;
        int dy = rem / 3;
        int dx = rem - dy * 3;
        int z = cz - 1 + dz, y = cy - 1 + dy, x = cx - 1 + dx;
        bool valid = (lane < 27) && (unsigned)z < GS && (unsigned)y < GS && (unsigned)x < GS;
        int cell = valid ? (z * GS + y) * GS + x : 0;
        int n = valid ? min(cnts[cell], CAP) : 0;
        const float4* row = pts + cell * CAP;
        // speculative first-4 loads (addresses independent of n; masked below)
        float4 p0 = row[0], p1 = row[1], p2 = row[2], p3 = row[3];
        float ddx, ddy, ddz;
        ddx = qx - p0.x; ddy = qy - p0.y; ddz = qz - p0.z;
        float d0 = fmaf(ddx, ddx, fmaf(ddy, ddy, ddz * ddz));
        ddx = qx - p1.x; ddy = qy - p1.y; ddz = qz - p1.z;
        float d1 = fmaf(ddx, ddx, fmaf(ddy, ddy, ddz * ddz));
        ddx = qx - p2.x; ddy = qy - p2.y; ddz = qz - p2.z;
        float d2 = fmaf(ddx, ddx, fmaf(ddy, ddy, ddz * ddz));
        ddx = qx - p3.x; ddy = qy - p3.y; ddz = qz - p3.z;
        float d3 = fmaf(ddx, ddx, fmaf(ddy, ddy, ddz * ddz));
        if (n > 0) best_l = fminf(best_l, d0);
        if (n > 1) best_l = fminf(best_l, d1);
        if (n > 2) best_l = fminf(best_l, d2);
        if (n > 3) best_l = fminf(best_l, d3);
        for (int k = 4; k < n; ++k) {
            float4 p = row[k];
            ddx = qx - p.x; ddy = qy - p.y; ddz = qz - p.z;
            best_l = fminf(best_l, fmaf(ddx, ddx, fmaf(ddy, ddy, ddz * ddz)));
        }
    }

    float bw = best_l;
    for (int o = 16; o > 0; o >>= 1)
        bw = fminf(bw, __shfl_xor_sync(0xFFFFFFFFu, bw, o));

    // margin: min distance from q to outside the 3x3x3 box. Edge cells hold all
    // clamped points beyond the domain -> +inf margin on grid-edge sides.
    float mxlo = (cx - 1 <= 0)      ? 1e30f : qx - (OX + (float)(cx - 1) * CELL_SZ);
    float mxhi = (cx + 1 >= GS - 1) ? 1e30f : (OX + (float)(cx + 2) * CELL_SZ) - qx;
    float mylo = (cy - 1 <= 0)      ? 1e30f : qy - (OX + (float)(cy - 1) * CELL_SZ);
    float myhi = (cy + 1 >= GS - 1) ? 1e30f : (OX + (float)(cy + 2) * CELL_SZ) - qy;
    float mzlo = (cz - 1 <= 0)      ? 1e30f : qz - (OX + (float)(cz - 1) * CELL_SZ);
    float mzhi = (cz + 1 >= GS - 1) ? 1e30f : (OX + (float)(cz + 2) * CELL_SZ) - qz;
    float m = fminf(fminf(fminf(mxlo, mxhi), fminf(mylo, myhi)), fminf(mzlo, mzhi));
    m = fmaxf(m, 0.0f);

    if (bw <= m * m) {
        // certified: only the (rare) overflow points could still beat it
        best_l = bw;
        int on = min(g_ovcnt[dir], OVCAP);
        for (int k = lane; k < on; k += 32) {
            float4 p = g_ovpts[dir][k];
            float ddx = qx - p.x, ddy = qy - p.y, ddz = qz - p.z;
            best_l = fminf(best_l, fmaf(ddx, ddx, fmaf(ddy, ddy, ddz * ddz)));
        }
    } else {
        // brute-force fallback: warp-parallel coalesced scan of ALL db points
        const float4* __restrict__ db = g_db[dir];
        best_l = bw;
#pragma unroll 4
        for (int k = lane; k < N_PTS; k += 32) {
            float4 p = db[k];
            float ddx = qx - p.x, ddy = qy - p.y, ddz = qz - p.z;
            best_l = fminf(best_l, fmaf(ddx, ddx, fmaf(ddy, ddy, ddz * ddz)));
        }
    }

    for (int o = 16; o > 0; o >>= 1)
        best_l = fminf(best_l, __shfl_xor_sync(0xFFFFFFFFu, best_l, o));

    // per-block deterministic sum, then last-block final reduction
    __shared__ float swarp[WARPS_PB];
    __shared__ int slast;
    if (lane == 0) swarp[threadIdx.x >> 5] = sqrtf(best_l);
    __syncthreads();
    if (threadIdx.x == 0) {
        float tot = 0.0f;
#pragma unroll
        for (int w = 0; w < WARPS_PB; ++w) tot += swarp[w];
        g_bsum[blockIdx.x] = tot;
        __threadfence();
        int prev = atomicAdd(&g_done, 1);
        slast = (prev == QBLOCKS - 1) ? 1 : 0;
    }
    __syncthreads();

    if (slast) {
        float s = 0.0f;
        for (int k = threadIdx.x; k < QBLOCKS; k += QTPB) s += g_bsum[k];
        for (int o = 16; o > 0; o >>= 1) s += __shfl_xor_sync(0xFFFFFFFFu, s, o);
        __shared__ float ssum[WARPS_PB];
        if ((threadIdx.x & 31) == 0) ssum[threadIdx.x >> 5] = s;
        __syncthreads();
        if (threadIdx.x == 0) {
            float tot = 0.0f;
#pragma unroll
            for (int w = 0; w < WARPS_PB; ++w) tot += ssum[w];
            out[0] = tot / (float)N_PTS;   // (sum_pred + sum_gt)/N = mean1 + mean2
        }
    }
}

extern "C" void kernel_launch(void* const* d_in, const int* in_sizes, int n_in,
                              void* d_out, int out_size) {
    const float* pred = (const float*)d_in[0];
    const float* gt   = (const float*)d_in[1];
    float* out = (float*)d_out;

    cd_zero<<<512, 256>>>();
    cd_build<<<(2 * N_PTS) / 256, 256>>>(pred, gt);
    cd_query<<<QBLOCKS, QTPB>>>(pred, gt, out);
}

// round 12
// speedup vs baseline: 2.7611x; 1.0758x over previous
#include <cuda_runtime.h>
#include <stdint.h>

#define N_PTS 16384
#define GS 64
#define NCELL (GS * GS * GS)           // 262144
#define CAP 16
#define OVCAP 1024
#define OX (-5.5f)
#define CELL_SZ 0.171875f              // 11/64
#define INV_CELL 5.8181818f            // 64/11
#define QTPB 256
#define QBLOCKS (2 * N_PTS * 32 / QTPB)  // 4096 (one warp per query)

#define FB_QPB 256                     // fallback queries per block chunk
#define FB_JT 1024                     // db points per fallback j-split
#define FB_JS (N_PTS / FB_JT)          // 16
#define FB_XB (N_PTS / FB_QPB)         // 64 (max chunks per dir)

__device__ int    g_cnt[2][NCELL];              // per-cell count / slot cursor
__device__ float4 g_cell_pts[2][NCELL * CAP];   // per-cell storage (sparse-hot, NOT zeroed: n-guards required)
__device__ float4 g_db[2][N_PTS];               // compact all-points array
__device__ int    g_ovcnt[2];
__device__ float4 g_ovpts[2][OVCAP];
__device__ int    g_nf[2];                      // fallback counts
__device__ int    g_flist[2][N_PTS];            // fallback query indices
__device__ unsigned int g_res[2][N_PTS];        // per-query min sq dist (float bits)

__global__ void cd_zero() {
    int i = blockIdx.x * blockDim.x + threadIdx.x;
    int stride = gridDim.x * blockDim.x;
    int* c = (int*)g_cnt;
    for (int k = i; k < 2 * NCELL; k += stride) c[k] = 0;
    if (i == 0) { g_ovcnt[0] = 0; g_ovcnt[1] = 0; g_nf[0] = 0; g_nf[1] = 0; }
}

__device__ __forceinline__ int cell_coord(float v) {
    int c = (int)floorf((v - OX) * INV_CELL);
    return min(max(c, 0), GS - 1);
}

__global__ void cd_build(const float* __restrict__ pred, const float* __restrict__ gt) {
    int t = blockIdx.x * blockDim.x + threadIdx.x;   // 0..32767
    int dir = t >> 14;
    int i = t & (N_PTS - 1);
    const float* P = dir ? pred : gt;                 // dir0 db=gt, dir1 db=pred
    float x = P[3 * i], y = P[3 * i + 1], z = P[3 * i + 2];
    float4 v = make_float4(x, y, z, 0.0f);
    g_db[dir][i] = v;
    int cx = cell_coord(x), cy = cell_coord(y), cz = cell_coord(z);
    int cell = (cz * GS + cy) * GS + cx;
    int slot = atomicAdd(&g_cnt[dir][cell], 1);
    if (slot < CAP) {
        g_cell_pts[dir][cell * CAP + slot] = v;
    } else {
        int o = atomicAdd(&g_ovcnt[dir], 1);
        if (o < OVCAP) g_ovpts[dir][o] = v;
    }
}

// One warp per query: r=1 probe. Certified -> write result. Else -> enqueue
// for the batched brute-force pass (result slot seeded with the r=1 bound).
__global__ void __launch_bounds__(QTPB) cd_query(
    const float* __restrict__ pred, const float* __restrict__ gt)
{
    const int wid  = (blockIdx.x * QTPB + threadIdx.x) >> 5;   // 0..32767
    const int lane = threadIdx.x & 31;
    const int dir  = wid >> 14;
    const int i    = wid & (N_PTS - 1);

    const float* Q = dir ? gt : pred;
    const float qx = Q[3 * i], qy = Q[3 * i + 1], qz = Q[3 * i + 2];
    const int cx = cell_coord(qx), cy = cell_coord(qy), cz = cell_coord(qz);

    const int*    __restrict__ cnts = g_cnt[dir];
    const float4* __restrict__ pts  = g_cell_pts[dir];

    float best_l = 3.402823466e+38f;

    // r=1 probe: lanes 0..26 cover the 3x3x3 box
    {
        int dz = lane / 9;
        int rem = lane - dz * 9;
        int dy = rem / 3;
        int dx = rem - dy * 3;
        int z = cz - 1 + dz, y = cy - 1 + dy, x = cx - 1 + dx;
        bool valid = (lane < 27) && (unsigned)z < GS && (unsigned)y < GS && (unsigned)x < GS;
        int cell = valid ? (z * GS + y) * GS + x : 0;
        int n = valid ? min(cnts[cell], CAP) : 0;
        const float4* row = pts + cell * CAP;
        // speculative first-4 loads; contents may be stale -> MUST stay n-guarded
        float4 p0 = row[0], p1 = row[1], p2 = row[2], p3 = row[3];
        float ddx, ddy, ddz;
        ddx = qx - p0.x; ddy = qy - p0.y; ddz = qz - p0.z;
        float d0 = fmaf(ddx, ddx, fmaf(ddy, ddy, ddz * ddz));
        ddx = qx - p1.x; ddy = qy - p1.y; ddz = qz - p1.z;
        float d1 = fmaf(ddx, ddx, fmaf(ddy, ddy, ddz * ddz));
        ddx = qx - p2.x; ddy = qy - p2.y; ddz = qz - p2.z;
        float d2 = fmaf(ddx, ddx, fmaf(ddy, ddy, ddz * ddz));
        ddx = qx - p3.x; ddy = qy - p3.y; ddz = qz - p3.z;
        float d3 = fmaf(ddx, ddx, fmaf(ddy, ddy, ddz * ddz));
        if (n > 0) best_l = fminf(best_l, d0);
        if (n > 1) best_l = fminf(best_l, d1);
        if (n > 2) best_l = fminf(best_l, d2);
        if (n > 3) best_l = fminf(best_l, d3);
        for (int k = 4; k < n; ++k) {
            float4 p = row[k];
            ddx = qx - p.x; ddy = qy - p.y; ddz = qz - p.z;
            best_l = fminf(best_l, fmaf(ddx, ddx, fmaf(ddy, ddy, ddz * ddz)));
        }
    }

    float bw = best_l;
    for (int o = 16; o > 0; o >>= 1)
        bw = fminf(bw, __shfl_xor_sync(0xFFFFFFFFu, bw, o));

    // margin to outside the 3x3x3 box; grid-edge sides hold all clamped points -> +inf
    float mxlo = (cx - 1 <= 0)      ? 1e30f : qx - (OX + (float)(cx - 1) * CELL_SZ);
    float mxhi = (cx + 1 >= GS - 1) ? 1e30f : (OX + (float)(cx + 2) * CELL_SZ) - qx;
    float mylo = (cy - 1 <= 0)      ? 1e30f : qy - (OX + (float)(cy - 1) * CELL_SZ);
    float myhi = (cy + 1 >= GS - 1) ? 1e30f : (OX + (float)(cy + 2) * CELL_SZ) - qy;
    float mzlo = (cz - 1 <= 0)      ? 1e30f : qz - (OX + (float)(cz - 1) * CELL_SZ);
    float mzhi = (cz + 1 >= GS - 1) ? 1e30f : (OX + (float)(cz + 2) * CELL_SZ) - qz;
    float m = fminf(fminf(fminf(mxlo, mxhi), fminf(mylo, myhi)), fminf(mzlo, mzhi));
    m = fmaxf(m, 0.0f);

    if (bw <= m * m) {
        // certified vs in-cell points; overflow points (tiny set) still required
        best_l = bw;
        int on = min(g_ovcnt[dir], OVCAP);
        for (int k = lane; k < on; k += 32) {
            float4 p = g_ovpts[dir][k];
            float ddx = qx - p.x, ddy = qy - p.y, ddz = qz - p.z;
            best_l = fminf(best_l, fmaf(ddx, ddx, fmaf(ddy, ddy, ddz * ddz)));
        }
        for (int o = 16; o > 0; o >>= 1)
            best_l = fminf(best_l, __shfl_xor_sync(0xFFFFFFFFu, best_l, o));
        if (lane == 0) g_res[dir][i] = __float_as_uint(fmaxf(best_l, 0.0f));
    } else {
        // enqueue for batched brute pass; seed slot with the r=1 upper bound
        if (lane == 0) {
            g_res[dir][i] = __float_as_uint(fmaxf(bw, 0.0f));
            int pos = atomicAdd(&g_nf[dir], 1);
            g_flist[dir][pos] = i;
        }
    }
}

// Batched brute force over the fallback set: 256 queries/block vs a 1024-point
// smem db tile -> db traffic amortized 256x. atomicMin merges j-splits.
__global__ void __launch_bounds__(FB_QPB) cd_fbrute(
    const float* __restrict__ pred, const float* __restrict__ gt)
{
    const int dir = blockIdx.z;
    const int nf = g_nf[dir];
    const int qbase = blockIdx.x * FB_QPB;
    if (qbase >= nf) return;

    __shared__ float4 tile[FB_JT];
    const int jb = blockIdx.y * FB_JT;
    const float4* __restrict__ db = g_db[dir];
#pragma unroll
    for (int k = threadIdx.x; k < FB_JT; k += FB_QPB)
        tile[k] = db[jb + k];
    __syncthreads();

    const int q = qbase + threadIdx.x;
    if (q >= nf) return;
    const int i = g_flist[dir][q];
    const float* Q = dir ? gt : pred;
    const float qx = Q[3 * i], qy = Q[3 * i + 1], qz = Q[3 * i + 2];

    float best = 3.402823466e+38f;
#pragma unroll 4
    for (int k = 0; k < FB_JT; ++k) {
        float4 p = tile[k];
        float ddx = qx - p.x, ddy = qy - p.y, ddz = qz - p.z;
        best = fminf(best, fmaf(ddx, ddx, fmaf(ddy, ddy, ddz * ddz)));
    }
    atomicMin(&g_res[dir][i], __float_as_uint(fmaxf(best, 0.0f)));
}

__global__ void cd_final(float* __restrict__ out) {
    const int t = threadIdx.x;           // 1024 threads
    const unsigned int* r = (const unsigned int*)g_res;
    float s = 0.0f;
    for (int k = t; k < 2 * N_PTS; k += 1024)
        s += sqrtf(__uint_as_float(r[k]));
    for (int o = 16; o > 0; o >>= 1) s += __shfl_xor_sync(0xFFFFFFFFu, s, o);
    __shared__ float ssum[32];
    if ((t & 31) == 0) ssum[t >> 5] = s;
    __syncthreads();
    if (t == 0) {
        float tot = 0.0f;
#pragma unroll
        for (int w = 0; w < 32; ++w) tot += ssum[w];
        out[0] = tot / (float)N_PTS;   // (sum_pred + sum_gt)/N = mean1 + mean2
    }
}

extern "C" void kernel_launch(void* const* d_in, const int* in_sizes, int n_in,
                              void* d_out, int out_size) {
    const float* pred = (const float*)d_in[0];
    const float* gt   = (const float*)d_in[1];
    float* out = (float*)d_out;

    cd_zero<<<512, 256>>>();
    cd_build<<<(2 * N_PTS) / 256, 256>>>(pred, gt);
    cd_query<<<QBLOCKS, QTPB>>>(pred, gt);
    dim3 fgrid(FB_XB, FB_JS, 2);        // (64, 16, 2); inactive chunks exit fast
    cd_fbrute<<<fgrid, FB_QPB>>>(pred, gt);
    cd_final<<<1, 1024>>>(out);
}

// round 13
// speedup vs baseline: 3.5702x; 1.2931x over previous
#include <cuda_runtime.h>
#include <stdint.h>

#define N_PTS 16384
#define GS 64
#define NCELL (GS * GS * GS)           // 262144
#define CAP 16
#define OVCAP 1024
#define OX (-5.5f)
#define CELL_SZ 0.171875f              // 11/64
#define INV_CELL 5.8181818f            // 64/11
#define QTPB 256
#define QBLOCKS (2 * N_PTS * 32 / QTPB)  // 4096 (one warp per query)

#define FB_QPB 256                     // fallback queries per block chunk
#define FB_JT 512                      // db points per fallback j-split
#define FB_JS (N_PTS / FB_JT)          // 32
#define FB_XB (N_PTS / FB_QPB)         // 64 (max chunks per dir)

__device__ int    g_cnt[2][NCELL];              // per-cell count / slot cursor
__device__ float4 g_cell_pts[2][NCELL * CAP];   // per-cell storage (NOT zeroed: n-guards required)
__device__ float4 g_db[2][N_PTS];               // compact points, w = -0.5*|p|^2
__device__ int    g_ovcnt[2];
__device__ float4 g_ovpts[2][OVCAP];
__device__ int    g_nf[2];                      // fallback counts
__device__ int    g_flist[2][N_PTS];            // fallback query indices
__device__ unsigned int g_res[2][N_PTS];        // per-query min sq dist (float bits)

__device__ __forceinline__ unsigned long long pack2(float lo, float hi) {
    unsigned long long r;
    asm("mov.b64 %0, {%1, %2};" : "=l"(r) : "f"(lo), "f"(hi));
    return r;
}
__device__ __forceinline__ unsigned long long fma2(
    unsigned long long a, unsigned long long b, unsigned long long c) {
    unsigned long long d;
    asm("fma.rn.f32x2 %0, %1, %2, %3;" : "=l"(d) : "l"(a), "l"(b), "l"(c));
    return d;
}
__device__ __forceinline__ void unpack2(unsigned long long v, float& lo, float& hi) {
    asm("mov.b64 {%0, %1}, %2;" : "=f"(lo), "=f"(hi) : "l"(v));
}

__global__ void cd_zero() {
    int i = blockIdx.x * blockDim.x + threadIdx.x;
    int stride = gridDim.x * blockDim.x;
    int* c = (int*)g_cnt;
    for (int k = i; k < 2 * NCELL; k += stride) c[k] = 0;
    if (i == 0) { g_ovcnt[0] = 0; g_ovcnt[1] = 0; g_nf[0] = 0; g_nf[1] = 0; }
}

__device__ __forceinline__ int cell_coord(float v) {
    int c = (int)floorf((v - OX) * INV_CELL);
    return min(max(c, 0), GS - 1);
}

__global__ void cd_build(const float* __restrict__ pred, const float* __restrict__ gt) {
    int t = blockIdx.x * blockDim.x + threadIdx.x;   // 0..32767
    int dir = t >> 14;
    int i = t & (N_PTS - 1);
    const float* P = dir ? pred : gt;                 // dir0 db=gt, dir1 db=pred
    float x = P[3 * i], y = P[3 * i + 1], z = P[3 * i + 2];
    float c = -0.5f * fmaf(x, x, fmaf(y, y, z * z));
    g_db[dir][i] = make_float4(x, y, z, c);
    int cx = cell_coord(x), cy = cell_coord(y), cz = cell_coord(z);
    int cell = (cz * GS + cy) * GS + cx;
    int slot = atomicAdd(&g_cnt[dir][cell], 1);
    if (slot < CAP) {
        g_cell_pts[dir][cell * CAP + slot] = make_float4(x, y, z, 0.0f);
    } else {
        int o = atomicAdd(&g_ovcnt[dir], 1);
        if (o < OVCAP) g_ovpts[dir][o] = make_float4(x, y, z, 0.0f);
    }
}

// One warp per query: r=1 probe. Certified -> write result. Else -> enqueue
// for the batched brute-force pass (result slot seeded with the r=1 bound).
__global__ void __launch_bounds__(QTPB) cd_query(
    const float* __restrict__ pred, const float* __restrict__ gt)
{
    const int wid  = (blockIdx.x * QTPB + threadIdx.x) >> 5;   // 0..32767
    const int lane = threadIdx.x & 31;
    const int dir  = wid >> 14;
    const int i    = wid & (N_PTS - 1);

    const float* Q = dir ? gt : pred;
    const float qx = Q[3 * i], qy = Q[3 * i + 1], qz = Q[3 * i + 2];
    const int cx = cell_coord(qx), cy = cell_coord(qy), cz = cell_coord(qz);

    const int*    __restrict__ cnts = g_cnt[dir];
    const float4* __restrict__ pts  = g_cell_pts[dir];

    float best_l = 3.402823466e+38f;

    // r=1 probe: lanes 0..26 cover the 3x3x3 box
    {
        int dz = lane / 9;
        int rem = lane - dz * 9;
        int dy = rem / 3;
        int dx = rem - dy * 3;
        int z = cz - 1 + dz, y = cy - 1 + dy, x = cx - 1 + dx;
        bool valid = (lane < 27) && (unsigned)z < GS && (unsigned)y < GS && (unsigned)x < GS;
        int cell = valid ? (z * GS + y) * GS + x : 0;
        int n = valid ? min(cnts[cell], CAP) : 0;
        const float4* row = pts + cell * CAP;
        // speculative first-4 loads; contents may be stale -> MUST stay n-guarded
        float4 p0 = row[0], p1 = row[1], p2 = row[2], p3 = row[3];
        float ddx, ddy, ddz;
        ddx = qx - p0.x; ddy = qy - p0.y; ddz = qz - p0.z;
        float d0 = fmaf(ddx, ddx, fmaf(ddy, ddy, ddz * ddz));
        ddx = qx - p1.x; ddy = qy - p1.y; ddz = qz - p1.z;
        float d1 = fmaf(ddx, ddx, fmaf(ddy, ddy, ddz * ddz));
        ddx = qx - p2.x; ddy = qy - p2.y; ddz = qz - p2.z;
        float d2 = fmaf(ddx, ddx, fmaf(ddy, ddy, ddz * ddz));
        ddx = qx - p3.x; ddy = qy - p3.y; ddz = qz - p3.z;
        float d3 = fmaf(ddx, ddx, fmaf(ddy, ddy, ddz * ddz));
        if (n > 0) best_l = fminf(best_l, d0);
        if (n > 1) best_l = fminf(best_l, d1);
        if (n > 2) best_l = fminf(best_l, d2);
        if (n > 3) best_l = fminf(best_l, d3);
        for (int k = 4; k < n; ++k) {
            float4 p = row[k];
            ddx = qx - p.x; ddy = qy - p.y; ddz = qz - p.z;
            best_l = fminf(best_l, fmaf(ddx, ddx, fmaf(ddy, ddy, ddz * ddz)));
        }
    }

    float bw = best_l;
    for (int o = 16; o > 0; o >>= 1)
        bw = fminf(bw, __shfl_xor_sync(0xFFFFFFFFu, bw, o));

    // margin to outside the 3x3x3 box; grid-edge sides hold all clamped points -> +inf
    float mxlo = (cx - 1 <= 0)      ? 1e30f : qx - (OX + (float)(cx - 1) * CELL_SZ);
    float mxhi = (cx + 1 >= GS - 1) ? 1e30f : (OX + (float)(cx + 2) * CELL_SZ) - qx;
    float mylo = (cy - 1 <= 0)      ? 1e30f : qy - (OX + (float)(cy - 1) * CELL_SZ);
    float myhi = (cy + 1 >= GS - 1) ? 1e30f : (OX + (float)(cy + 2) * CELL_SZ) - qy;
    float mzlo = (cz - 1 <= 0)      ? 1e30f : qz - (OX + (float)(cz - 1) * CELL_SZ);
    float mzhi = (cz + 1 >= GS - 1) ? 1e30f : (OX + (float)(cz + 2) * CELL_SZ) - qz;
    float m = fminf(fminf(fminf(mxlo, mxhi), fminf(mylo, myhi)), fminf(mzlo, mzhi));
    m = fmaxf(m, 0.0f);

    if (bw <= m * m) {
        // certified vs in-cell points; overflow points (tiny set) still required
        best_l = bw;
        int on = min(g_ovcnt[dir], OVCAP);
        for (int k = lane; k < on; k += 32) {
            float4 p = g_ovpts[dir][k];
            float ddx = qx - p.x, ddy = qy - p.y, ddz = qz - p.z;
            best_l = fminf(best_l, fmaf(ddx, ddx, fmaf(ddy, ddy, ddz * ddz)));
        }
        for (int o = 16; o > 0; o >>= 1)
            best_l = fminf(best_l, __shfl_xor_sync(0xFFFFFFFFu, best_l, o));
        if (lane == 0) g_res[dir][i] = __float_as_uint(fmaxf(best_l, 0.0f));
    } else {
        // enqueue for batched brute pass; seed slot with the r=1 upper bound
        if (lane == 0) {
            g_res[dir][i] = __float_as_uint(fmaxf(bw, 0.0f));
            int pos = atomicAdd(&g_nf[dir], 1);
            g_flist[dir][pos] = i;
        }
    }
}

// Batched brute force over the fallback set, packed-f32x2 dot-trick inner loop.
// d2 = |q|^2 - 2*max_j (q.p_j - 0.5|p_j|^2); c = -0.5|p|^2 baked into g_db.w.
__global__ void __launch_bounds__(FB_QPB) cd_fbrute(
    const float* __restrict__ pred, const float* __restrict__ gt)
{
    const int dir = blockIdx.z;
    const int nf = g_nf[dir];
    const int qbase = blockIdx.x * FB_QPB;
    if (qbase >= nf) return;

    __shared__ ulonglong2 tile_xy[FB_JT / 2];   // (x0,x1),(y0,y1)
    __shared__ ulonglong2 tile_zc[FB_JT / 2];   // (z0,z1),(c0,c1)
    const int jb = blockIdx.y * FB_JT;
    const float4* __restrict__ db = g_db[dir];
    if (threadIdx.x < FB_JT / 2) {
        float4 a = db[jb + 2 * threadIdx.x];
        float4 b = db[jb + 2 * threadIdx.x + 1];
        tile_xy[threadIdx.x] = make_ulonglong2(pack2(a.x, b.x), pack2(a.y, b.y));
        tile_zc[threadIdx.x] = make_ulonglong2(pack2(a.z, b.z), pack2(a.w, b.w));
    }
    __syncthreads();

    const int q = qbase + threadIdx.x;
    if (q >= nf) return;
    const int i = g_flist[dir][q];
    const float* Q = dir ? gt : pred;
    const float qx = Q[3 * i], qy = Q[3 * i + 1], qz = Q[3 * i + 2];
    const unsigned long long pqx = pack2(qx, qx);
    const unsigned long long pqy = pack2(qy, qy);
    const unsigned long long pqz = pack2(qz, qz);

    float best0 = -3.402823466e+38f, best1 = -3.402823466e+38f;
#pragma unroll 8
    for (int k = 0; k < FB_JT / 2; ++k) {
        const ulonglong2 xy = tile_xy[k];   // LDS.128 broadcast
        const ulonglong2 zc = tile_zc[k];
        unsigned long long tt = fma2(pqx, xy.x, zc.y);
        tt = fma2(pqy, xy.y, tt);
        tt = fma2(pqz, zc.x, tt);
        float t0, t1;
        unpack2(tt, t0, t1);
        best0 = fmaxf(best0, t0);
        best1 = fmaxf(best1, t1);
    }
    float bmax = fmaxf(best0, best1);
    float q2 = fmaf(qx, qx, fmaf(qy, qy, qz * qz));
    float d2 = fmaxf(fmaf(-2.0f, bmax, q2), 0.0f);
    atomicMin(&g_res[dir][i], __float_as_uint(d2));
}

__global__ void cd_final(float* __restrict__ out) {
    const int t = threadIdx.x;           // 1024 threads
    const unsigned int* r = (const unsigned int*)g_res;
    float s = 0.0f;
    for (int k = t; k < 2 * N_PTS; k += 1024)
        s += sqrtf(__uint_as_float(r[k]));
    for (int o = 16; o > 0; o >>= 1) s += __shfl_xor_sync(0xFFFFFFFFu, s, o);
    __shared__ float ssum[32];
    if ((t & 31) == 0) ssum[t >> 5] = s;
    __syncthreads();
    if (t == 0) {
        float tot = 0.0f;
#pragma unroll
        for (int w = 0; w < 32; ++w) tot += ssum[w];
        out[0] = tot / (float)N_PTS;   // (sum_pred + sum_gt)/N = mean1 + mean2
    }
}

extern "C" void kernel_launch(void* const* d_in, const int* in_sizes, int n_in,
                              void* d_out, int out_size) {
    const float* pred = (const float*)d_in[0];
    const float* gt   = (const float*)d_in[1];
    float* out = (float*)d_out;

    cd_zero<<<512, 256>>>();
    cd_build<<<(2 * N_PTS) / 256, 256>>>(pred, gt);
    cd_query<<<QBLOCKS, QTPB>>>(pred, gt);
    dim3 fgrid(FB_XB, FB_JS, 2);        // (64, 32, 2); inactive chunks exit fast
    cd_fbrute<<<fgrid, FB_QPB>>>(pred, gt);
    cd_final<<<1, 1024>>>(out);
}

// round 14
// speedup vs baseline: 4.2265x; 1.1838x over previous
#include <cuda_runtime.h>
#include <stdint.h>

#define N_PTS 16384
#define GS 64
#define NCELL (GS * GS * GS)           // 262144
#define CAP 16
#define OVCAP 1024
#define OX (-5.5f)
#define CELL_SZ 0.171875f              // 11/64
#define INV_CELL 5.8181818f            // 64/11
#define QTPB 256
#define QBLOCKS (2 * N_PTS * 32 / QTPB)  // 4096 (one warp per query)

#define FB_QPB 256                     // fallback queries per block chunk
#define FB_JT 512                      // db points per fallback j-split
#define FB_JS (N_PTS / FB_JT)          // 32
#define FB_XB (N_PTS / FB_QPB)         // 64 (max chunks per dir)

__device__ int    g_cnt[2][NCELL];              // per-cell count / slot cursor
__device__ float4 g_cell_pts[2][NCELL * CAP];   // per-cell storage (NOT zeroed: n-guards required)
__device__ float4 g_db[2][N_PTS];               // compact points, w = -0.5*|p|^2
__device__ int    g_ovcnt[2];
__device__ float4 g_ovpts[2][OVCAP];
__device__ int    g_nf[2];                      // fallback counts
__device__ int    g_flist[2][N_PTS];            // fallback query indices
__device__ unsigned int g_res[2][N_PTS];        // per-query min sq dist (float bits)

__device__ __forceinline__ unsigned long long pack2(float lo, float hi) {
    unsigned long long r;
    asm("mov.b64 %0, {%1, %2};" : "=l"(r) : "f"(lo), "f"(hi));
    return r;
}
__device__ __forceinline__ unsigned long long fma2(
    unsigned long long a, unsigned long long b, unsigned long long c) {
    unsigned long long d;
    asm("fma.rn.f32x2 %0, %1, %2, %3;" : "=l"(d) : "l"(a), "l"(b), "l"(c));
    return d;
}
__device__ __forceinline__ void unpack2(unsigned long long v, float& lo, float& hi) {
    asm("mov.b64 {%0, %1}, %2;" : "=f"(lo), "=f"(hi) : "l"(v));
}

__global__ void cd_zero() {
    int i = blockIdx.x * blockDim.x + threadIdx.x;
    int stride = gridDim.x * blockDim.x;
    int* c = (int*)g_cnt;
    for (int k = i; k < 2 * NCELL; k += stride) c[k] = 0;
    if (i == 0) { g_ovcnt[0] = 0; g_ovcnt[1] = 0; g_nf[0] = 0; g_nf[1] = 0; }
}

__device__ __forceinline__ int cell_coord(float v) {
    int c = (int)floorf((v - OX) * INV_CELL);
    return min(max(c, 0), GS - 1);
}

__global__ void cd_build(const float* __restrict__ pred, const float* __restrict__ gt) {
    int t = blockIdx.x * blockDim.x + threadIdx.x;   // 0..32767
    int dir = t >> 14;
    int i = t & (N_PTS - 1);
    const float* P = dir ? pred : gt;                 // dir0 db=gt, dir1 db=pred
    float x = P[3 * i], y = P[3 * i + 1], z = P[3 * i + 2];
    float c = -0.5f * fmaf(x, x, fmaf(y, y, z * z));
    g_db[dir][i] = make_float4(x, y, z, c);
    int cx = cell_coord(x), cy = cell_coord(y), cz = cell_coord(z);
    int cell = (cz * GS + cy) * GS + cx;
    int slot = atomicAdd(&g_cnt[dir][cell], 1);
    if (slot < CAP) {
        g_cell_pts[dir][cell * CAP + slot] = make_float4(x, y, z, 0.0f);
    } else {
        int o = atomicAdd(&g_ovcnt[dir], 1);
        if (o < OVCAP) g_ovpts[dir][o] = make_float4(x, y, z, 0.0f);
    }
}

// Margin from q to outside box [c-r, c+r]^3 (cells). Grid-edge faces hold all
// clamped points beyond the domain -> +inf margin on those sides.
__device__ __forceinline__ float box_margin(
    float qx, float qy, float qz, int cx, int cy, int cz, int r)
{
    float mxlo = (cx - r <= 0)      ? 1e30f : qx - (OX + (float)(cx - r) * CELL_SZ);
    float mxhi = (cx + r >= GS - 1) ? 1e30f : (OX + (float)(cx + r + 1) * CELL_SZ) - qx;
    float mylo = (cy - r <= 0)      ? 1e30f : qy - (OX + (float)(cy - r) * CELL_SZ);
    float myhi = (cy + r >= GS - 1) ? 1e30f : (OX + (float)(cy + r + 1) * CELL_SZ) - qy;
    float mzlo = (cz - r <= 0)      ? 1e30f : qz - (OX + (float)(cz - r) * CELL_SZ);
    float mzhi = (cz + r >= GS - 1) ? 1e30f : (OX + (float)(cz + r + 1) * CELL_SZ) - qz;
    float m = fminf(fminf(fminf(mxlo, mxhi), fminf(mylo, myhi)), fminf(mzlo, mzhi));
    return fmaxf(m, 0.0f);
}

// One warp per query: r=1 probe, then r=2 shell for the uncertified tail;
// still-uncertified queries go to the batched brute pass.
__global__ void __launch_bounds__(QTPB) cd_query(
    const float* __restrict__ pred, const float* __restrict__ gt)
{
    const int wid  = (blockIdx.x * QTPB + threadIdx.x) >> 5;   // 0..32767
    const int lane = threadIdx.x & 31;
    const int dir  = wid >> 14;
    const int i    = wid & (N_PTS - 1);

    const float* Q = dir ? gt : pred;
    const float qx = Q[3 * i], qy = Q[3 * i + 1], qz = Q[3 * i + 2];
    const int cx = cell_coord(qx), cy = cell_coord(qy), cz = cell_coord(qz);

    const int*    __restrict__ cnts = g_cnt[dir];
    const float4* __restrict__ pts  = g_cell_pts[dir];

    float best_l = 3.402823466e+38f;

    // ---- r=1 probe: lanes 0..26 cover the 3x3x3 box ----
    {
        int dz = lane / 9;
        int rem = lane - dz * 9;
        int dy = rem / 3;
        int dx = rem - dy * 3;
        int z = cz - 1 + dz, y = cy - 1 + dy, x = cx - 1 + dx;
        bool valid = (lane < 27) && (unsigned)z < GS && (unsigned)y < GS && (unsigned)x < GS;
        int cell = valid ? (z * GS + y) * GS + x : 0;
        int n = valid ? min(cnts[cell], CAP) : 0;
        const float4* row = pts + cell * CAP;
        // speculative first-4 loads; contents may be stale -> MUST stay n-guarded
        float4 p0 = row[0], p1 = row[1], p2 = row[2], p3 = row[3];
        float ddx, ddy, ddz;
        ddx = qx - p0.x; ddy = qy - p0.y; ddz = qz - p0.z;
        float d0 = fmaf(ddx, ddx, fmaf(ddy, ddy, ddz * ddz));
        ddx = qx - p1.x; ddy = qy - p1.y; ddz = qz - p1.z;
        float d1 = fmaf(ddx, ddx, fmaf(ddy, ddy, ddz * ddz));
        ddx = qx - p2.x; ddy = qy - p2.y; ddz = qz - p2.z;
        float d2 = fmaf(ddx, ddx, fmaf(ddy, ddy, ddz * ddz));
        ddx = qx - p3.x; ddy = qy - p3.y; ddz = qz - p3.z;
        float d3 = fmaf(ddx, ddx, fmaf(ddy, ddy, ddz * ddz));
        if (n > 0) best_l = fminf(best_l, d0);
        if (n > 1) best_l = fminf(best_l, d1);
        if (n > 2) best_l = fminf(best_l, d2);
        if (n > 3) best_l = fminf(best_l, d3);
        for (int k = 4; k < n; ++k) {
            float4 p = row[k];
            ddx = qx - p.x; ddy = qy - p.y; ddz = qz - p.z;
            best_l = fminf(best_l, fmaf(ddx, ddx, fmaf(ddy, ddy, ddz * ddz)));
        }
    }

    float bw = best_l;
    for (int o = 16; o > 0; o >>= 1)
        bw = fminf(bw, __shfl_xor_sync(0xFFFFFFFFu, bw, o));

    float m1 = box_margin(qx, qy, qz, cx, cy, cz, 1);
    bool certified = (bw <= m1 * m1);

    // ---- r=2 shell (98 cells) for the uncertified tail ----
    if (!certified) {
        for (int base = 0; base < 125; base += 32) {
            int ci = base + lane;
            if (ci < 125) {
                int dz = ci / 25;
                int rem = ci - dz * 25;
                int dy = rem / 5;
                int dx = rem - dy * 5;
                int cheb = max(max(abs(dz - 2), abs(dy - 2)), abs(dx - 2));
                int z = cz - 2 + dz, y = cy - 2 + dy, x = cx - 2 + dx;
                bool ok = (cheb == 2) &&
                          (unsigned)z < GS && (unsigned)y < GS && (unsigned)x < GS;
                if (ok) {
                    int cell = (z * GS + y) * GS + x;
                    int n = min(cnts[cell], CAP);
                    const float4* row = pts + cell * CAP;
                    for (int k = 0; k < n; ++k) {
                        float4 p = row[k];
                        float ddx = qx - p.x, ddy = qy - p.y, ddz = qz - p.z;
                        best_l = fminf(best_l, fmaf(ddx, ddx, fmaf(ddy, ddy, ddz * ddz)));
                    }
                }
            }
        }
        bw = best_l;
        for (int o = 16; o > 0; o >>= 1)
            bw = fminf(bw, __shfl_xor_sync(0xFFFFFFFFu, bw, o));
        float m2 = box_margin(qx, qy, qz, cx, cy, cz, 2);
        certified = (bw <= m2 * m2);
    }

    if (certified) {
        // certified vs in-cell points; overflow points (tiny set) still required
        best_l = bw;
        int on = min(g_ovcnt[dir], OVCAP);
        for (int k = lane; k < on; k += 32) {
            float4 p = g_ovpts[dir][k];
            float ddx = qx - p.x, ddy = qy - p.y, ddz = qz - p.z;
            best_l = fminf(best_l, fmaf(ddx, ddx, fmaf(ddy, ddy, ddz * ddz)));
        }
        for (int o = 16; o > 0; o >>= 1)
            best_l = fminf(best_l, __shfl_xor_sync(0xFFFFFFFFu, best_l, o));
        if (lane == 0) g_res[dir][i] = __float_as_uint(fmaxf(best_l, 0.0f));
    } else {
        // enqueue for batched brute pass; seed slot with the current upper bound
        if (lane == 0) {
            g_res[dir][i] = __float_as_uint(fmaxf(bw, 0.0f));
            int pos = atomicAdd(&g_nf[dir], 1);
            g_flist[dir][pos] = i;
        }
    }
}

// Batched brute force over the fallback set, packed-f32x2 dot-trick inner loop.
// d2 = |q|^2 - 2*max_j (q.p_j - 0.5|p_j|^2); c = -0.5|p|^2 baked into g_db.w.
__global__ void __launch_bounds__(FB_QPB) cd_fbrute(
    const float* __restrict__ pred, const float* __restrict__ gt)
{
    const int dir = blockIdx.z;
    const int nf = g_nf[dir];
    const int qbase = blockIdx.x * FB_QPB;
    if (qbase >= nf) return;

    __shared__ ulonglong2 tile_xy[FB_JT / 2];   // (x0,x1),(y0,y1)
    __shared__ ulonglong2 tile_zc[FB_JT / 2];   // (z0,z1),(c0,c1)
    const int jb = blockIdx.y * FB_JT;
    const float4* __restrict__ db = g_db[dir];
    if (threadIdx.x < FB_JT / 2) {
        float4 a = db[jb + 2 * threadIdx.x];
        float4 b = db[jb + 2 * threadIdx.x + 1];
        tile_xy[threadIdx.x] = make_ulonglong2(pack2(a.x, b.x), pack2(a.y, b.y));
        tile_zc[threadIdx.x] = make_ulonglong2(pack2(a.z, b.z), pack2(a.w, b.w));
    }
    __syncthreads();

    const int q = qbase + threadIdx.x;
    if (q >= nf) return;
    const int i = g_flist[dir][q];
    const float* Q = dir ? gt : pred;
    const float qx = Q[3 * i], qy = Q[3 * i + 1], qz = Q[3 * i + 2];
    const unsigned long long pqx = pack2(qx, qx);
    const unsigned long long pqy = pack2(qy, qy);
    const unsigned long long pqz = pack2(qz, qz);

    float best0 = -3.402823466e+38f, best1 = -3.402823466e+38f;
#pragma unroll 8
    for (int k = 0; k < FB_JT / 2; ++k) {
        const ulonglong2 xy = tile_xy[k];   // LDS.128 broadcast
        const ulonglong2 zc = tile_zc[k];
        unsigned long long tt = fma2(pqx, xy.x, zc.y);
        tt = fma2(pqy, xy.y, tt);
        tt = fma2(pqz, zc.x, tt);
        float t0, t1;
        unpack2(tt, t0, t1);
        best0 = fmaxf(best0, t0);
        best1 = fmaxf(best1, t1);
    }
    float bmax = fmaxf(best0, best1);
    float q2 = fmaf(qx, qx, fmaf(qy, qy, qz * qz));
    float d2 = fmaxf(fmaf(-2.0f, bmax, q2), 0.0f);
    atomicMin(&g_res[dir][i], __float_as_uint(d2));
}

__global__ void cd_final(float* __restrict__ out) {
    const int t = threadIdx.x;           // 1024 threads
    const unsigned int* r = (const unsigned int*)g_res;
    float s = 0.0f;
    for (int k = t; k < 2 * N_PTS; k += 1024)
        s += sqrtf(__uint_as_float(r[k]));
    for (int o = 16; o > 0; o >>= 1) s += __shfl_xor_sync(0xFFFFFFFFu, s, o);
    __shared__ float ssum[32];
    if ((t & 31) == 0) ssum[t >> 5] = s;
    __syncthreads();
    if (t == 0) {
        float tot = 0.0f;
#pragma unroll
        for (int w = 0; w < 32; ++w) tot += ssum[w];
        out[0] = tot / (float)N_PTS;   // (sum_pred + sum_gt)/N = mean1 + mean2
    }
}

extern "C" void kernel_launch(void* const* d_in, const int* in_sizes, int n_in,
                              void* d_out, int out_size) {
    const float* pred = (const float*)d_in[0];
    const float* gt   = (const float*)d_in[1];
    float* out = (float*)d_out;

    cd_zero<<<512, 256>>>();
    cd_build<<<(2 * N_PTS) / 256, 256>>>(pred, gt);
    cd_query<<<QBLOCKS, QTPB>>>(pred, gt);
    dim3 fgrid(FB_XB, FB_JS, 2);        // (64, 32, 2); inactive chunks exit fast
    cd_fbrute<<<fgrid, FB_QPB>>>(pred, gt);
    cd_final<<<1, 1024>>>(out);
}